// round 4
// baseline (speedup 1.0000x reference)
#include <cuda_runtime.h>

#define D_IN   1024
#define DMODEL 1024
#define BB     4
#define NN     2048
#define NH     16
#define HD     64
#define MTOT   (BB*NN)   // 8192

// Scratch (device globals: allocation-free rule)
__device__ float g_q[(size_t)BB*NH*NN*HD];
__device__ float g_k[(size_t)BB*NH*NN*HD];
__device__ float g_v[(size_t)BB*NH*NN*HD];
__device__ float g_ctx[(size_t)MTOT*DMODEL];

// ---------------------------------------------------------------------------
// SGEMM: C[128x128] tile, K-tiles of 16, 256 threads, 8x8 strided micro-tile.
// mode 0: A = X, W selected by blockIdx.z (Wq/Wk/Wv), scatter into g_q/g_k/g_v
//         laid out [b, h, n, d].
// mode 1: A = g_ctx, W = W0, out = A@W + bias (row-major [8192,1024]).
// ---------------------------------------------------------------------------
__global__ __launch_bounds__(256)
void sgemm_kernel(const float* __restrict__ Xp,
                  const float* __restrict__ W0,
                  const float* __restrict__ W1,
                  const float* __restrict__ W2,
                  const float* __restrict__ bias,
                  float* __restrict__ outp,
                  int mode)
{
    __shared__ float As[2][16][128];
    __shared__ float Bs[2][16][128];

    const int tid = threadIdx.x;
    const int tx  = tid & 15;
    const int ty  = tid >> 4;
    const int bx  = blockIdx.x;
    const int by  = blockIdx.y;
    const int z   = blockIdx.z;

    const float* A = (mode == 0) ? Xp : (const float*)g_ctx;
    const float* W = (mode == 0) ? ((z == 0) ? W0 : (z == 1) ? W1 : W2) : W0;

    const float* Abase = A + (size_t)by * 128 * D_IN;
    const float* Bbase = W + bx * 128;

    float c[8][8];
#pragma unroll
    for (int i = 0; i < 8; i++)
#pragma unroll
        for (int j = 0; j < 8; j++) c[i][j] = 0.f;

    float4 pa[2], pb[2];

    // preload tile 0
#pragma unroll
    for (int l = 0; l < 2; l++) {
        int idx = tid + l * 256;
        int ar = idx >> 2, ac = idx & 3;
        pa[l] = *(const float4*)(Abase + (size_t)ar * D_IN + ac * 4);
        int br = idx >> 5, bc = idx & 31;
        pb[l] = *(const float4*)(Bbase + (size_t)br * DMODEL + bc * 4);
    }
#pragma unroll
    for (int l = 0; l < 2; l++) {
        int idx = tid + l * 256;
        int ar = idx >> 2, ac = (idx & 3) * 4;
        As[0][ac + 0][ar] = pa[l].x;
        As[0][ac + 1][ar] = pa[l].y;
        As[0][ac + 2][ar] = pa[l].z;
        As[0][ac + 3][ar] = pa[l].w;
        int br = idx >> 5, bc = (idx & 31) * 4;
        *(float4*)&Bs[0][br][bc] = pb[l];
    }
    __syncthreads();

    const int KT = D_IN / 16;  // 64
    for (int kt = 0; kt < KT; kt++) {
        int cur = kt & 1, nxt = cur ^ 1;
        if (kt < KT - 1) {
#pragma unroll
            for (int l = 0; l < 2; l++) {
                int idx = tid + l * 256;
                int ar = idx >> 2, ac = idx & 3;
                pa[l] = *(const float4*)(Abase + (size_t)ar * D_IN + (kt + 1) * 16 + ac * 4);
                int br = idx >> 5, bc = idx & 31;
                pb[l] = *(const float4*)(Bbase + (size_t)((kt + 1) * 16 + br) * DMODEL + bc * 4);
            }
        }
#pragma unroll
        for (int kk = 0; kk < 16; kk++) {
            float a[8], b[8];
#pragma unroll
            for (int i = 0; i < 8; i++) a[i] = As[cur][kk][ty + 16 * i];
#pragma unroll
            for (int j = 0; j < 8; j++) b[j] = Bs[cur][kk][tx + 16 * j];
#pragma unroll
            for (int i = 0; i < 8; i++)
#pragma unroll
                for (int j = 0; j < 8; j++) c[i][j] += a[i] * b[j];
        }
        if (kt < KT - 1) {
            __syncthreads();
#pragma unroll
            for (int l = 0; l < 2; l++) {
                int idx = tid + l * 256;
                int ar = idx >> 2, ac = (idx & 3) * 4;
                As[nxt][ac + 0][ar] = pa[l].x;
                As[nxt][ac + 1][ar] = pa[l].y;
                As[nxt][ac + 2][ar] = pa[l].z;
                As[nxt][ac + 3][ar] = pa[l].w;
                int br = idx >> 5, bc = (idx & 31) * 4;
                *(float4*)&Bs[nxt][br][bc] = pb[l];
            }
            __syncthreads();
        }
    }

    if (mode == 0) {
        float* O = (z == 0) ? g_q : (z == 1) ? g_k : g_v;
#pragma unroll
        for (int i = 0; i < 8; i++) {
            int m = by * 128 + ty + 16 * i;
            int b_ = m >> 11, n_ = m & (NN - 1);
#pragma unroll
            for (int j = 0; j < 8; j++) {
                int col = bx * 128 + tx + 16 * j;
                int h_ = col >> 6, d_ = col & (HD - 1);
                O[(((size_t)(b_ * NH + h_)) * NN + n_) * HD + d_] = c[i][j];
            }
        }
    } else {
#pragma unroll
        for (int i = 0; i < 8; i++) {
            int m = by * 128 + ty + 16 * i;
#pragma unroll
            for (int j = 0; j < 8; j++) {
                int col = bx * 128 + tx + 16 * j;
                outp[(size_t)m * DMODEL + col] = c[i][j] + bias[col];
            }
        }
    }
}

// ---------------------------------------------------------------------------
// Flash attention, causal. One block per (q-tile of 64 rows, batch*head).
// 256 threads, 4x4 strided fragments. K transposed with XOR swizzle; the K
// buffer is reused for the P tile (48 KB static smem total -> 3 CTAs/SM).
// ---------------------------------------------------------------------------
__global__ __launch_bounds__(256)
void attn_kernel()
{
    __shared__ float Qs[64][64];
    __shared__ float KP[64][64];   // Kt[kk][c ^ (kk&31)], then P[r][c]
    __shared__ float Vs[64][64];

    const int tid = threadIdx.x;
    const int tx  = tid & 15;
    const int ty  = tid >> 4;
    const int qt  = blockIdx.x;
    const int bh  = blockIdx.y;

    const float* Qg = g_q + ((size_t)bh * NN + qt * 64) * HD;
    const float* Kg = g_k + (size_t)bh * NN * HD;
    const float* Vg = g_v + (size_t)bh * NN * HD;

    // load Q tile (coalesced, conflict-free stores)
#pragma unroll
    for (int p = 0; p < 16; p++) {
        int li = p * 256 + tid;
        Qs[li >> 6][li & 63] = Qg[li];
    }

    float m_i[4], l_i[4], o[4][4];
#pragma unroll
    for (int i = 0; i < 4; i++) {
        m_i[i] = -1e30f;
        l_i[i] = 0.f;
#pragma unroll
        for (int j = 0; j < 4; j++) o[i][j] = 0.f;
    }

    for (int kt = 0; kt <= qt; kt++) {
        __syncthreads();  // prior reads of KP/Vs done (and Q visible on iter 0)
        const float* Ktg = Kg + (size_t)kt * 64 * HD;
        const float* Vtg = Vg + (size_t)kt * 64 * HD;
#pragma unroll
        for (int p = 0; p < 16; p++) {
            int li = p * 256 + tid;
            int r = li >> 6, d = li & 63;
            KP[d][r ^ (d & 31)] = Ktg[li];   // transposed + swizzled: conflict-free
            Vs[r][d] = Vtg[li];
        }
        __syncthreads();

        // S = Q K^T
        float s[4][4];
#pragma unroll
        for (int i = 0; i < 4; i++)
#pragma unroll
            for (int j = 0; j < 4; j++) s[i][j] = 0.f;

#pragma unroll 8
        for (int kk = 0; kk < 64; kk++) {
            float a[4], b[4];
#pragma unroll
            for (int i = 0; i < 4; i++) a[i] = Qs[ty + 16 * i][kk];
#pragma unroll
            for (int j = 0; j < 4; j++) b[j] = KP[kk][(tx + 16 * j) ^ (kk & 31)];
#pragma unroll
            for (int i = 0; i < 4; i++)
#pragma unroll
                for (int j = 0; j < 4; j++) s[i][j] += a[i] * b[j];
        }

        const float sc = 0.125f;  // 1/sqrt(64)
        if (kt == qt) {
#pragma unroll
            for (int i = 0; i < 4; i++)
#pragma unroll
                for (int j = 0; j < 4; j++)
                    s[i][j] = (tx + 16 * j > ty + 16 * i) ? -1e30f : s[i][j] * sc;
        } else {
#pragma unroll
            for (int i = 0; i < 4; i++)
#pragma unroll
                for (int j = 0; j < 4; j++) s[i][j] *= sc;
        }

        // online softmax (rows are owned by the 16 lanes sharing ty -> 16-lane xor reduce)
#pragma unroll
        for (int i = 0; i < 4; i++) {
            float mx = s[i][0];
#pragma unroll
            for (int j = 1; j < 4; j++) mx = fmaxf(mx, s[i][j]);
#pragma unroll
            for (int off = 8; off; off >>= 1)
                mx = fmaxf(mx, __shfl_xor_sync(0xffffffffu, mx, off));
            float mnew = fmaxf(m_i[i], mx);
            float cf = __expf(m_i[i] - mnew);
            m_i[i] = mnew;
            float rs = 0.f;
#pragma unroll
            for (int j = 0; j < 4; j++) { s[i][j] = __expf(s[i][j] - mnew); rs += s[i][j]; }
#pragma unroll
            for (int off = 8; off; off >>= 1)
                rs += __shfl_xor_sync(0xffffffffu, rs, off);
            l_i[i] = l_i[i] * cf + rs;
#pragma unroll
            for (int j = 0; j < 4; j++) o[i][j] *= cf;
        }

        __syncthreads();  // everyone done reading KP as Kt
#pragma unroll
        for (int i = 0; i < 4; i++)
#pragma unroll
            for (int j = 0; j < 4; j++)
                KP[ty + 16 * i][tx + 16 * j] = s[i][j];
        __syncthreads();

        // O += P V
#pragma unroll 8
        for (int j = 0; j < 64; j++) {
            float a[4], b[4];
#pragma unroll
            for (int i = 0; i < 4; i++) a[i] = KP[ty + 16 * i][j];
#pragma unroll
            for (int jj = 0; jj < 4; jj++) b[jj] = Vs[j][tx + 16 * jj];
#pragma unroll
            for (int i = 0; i < 4; i++)
#pragma unroll
                for (int jj = 0; jj < 4; jj++) o[i][jj] += a[i] * b[jj];
        }
    }

    // normalize + write ctx in [b, n, h*64+d] layout for the output GEMM
    const int b_ = bh >> 4, h_ = bh & 15;
#pragma unroll
    for (int i = 0; i < 4; i++) {
        int n_ = qt * 64 + ty + 16 * i;
        float inv = 1.f / l_i[i];
#pragma unroll
        for (int jj = 0; jj < 4; jj++) {
            int dc = tx + 16 * jj;
            g_ctx[((size_t)(b_ * NN + n_)) * DMODEL + h_ * HD + dc] = o[i][jj] * inv;
        }
    }
}

// ---------------------------------------------------------------------------
extern "C" void kernel_launch(void* const* d_in, const int* in_sizes, int n_in,
                              void* d_out, int out_size)
{
    const float* x  = (const float*)d_in[0];
    const float* Wq = (const float*)d_in[1];
    const float* Wk = (const float*)d_in[2];
    const float* Wv = (const float*)d_in[3];
    const float* Wo = (const float*)d_in[4];
    const float* bo = (const float*)d_in[5];
    float* out = (float*)d_out;

    // QKV projections: [8192,1024] x [1024,1024] x3, scattered to [b,h,n,d]
    sgemm_kernel<<<dim3(8, 64, 3), 256>>>(x, Wq, Wk, Wv, nullptr, nullptr, 0);
    // causal flash attention per (q-tile, b*h)
    attn_kernel<<<dim3(32, 64), 256>>>();
    // output projection + bias
    sgemm_kernel<<<dim3(8, 64, 1), 256>>>(nullptr, Wo, nullptr, nullptr, bo, out, 1);
}

// round 6
// speedup vs baseline: 3.1597x; 3.1597x over previous
#include <cuda_runtime.h>
#include <cstdint>

#define D_IN   1024
#define DMODEL 1024
#define BB     4
#define NN     2048
#define NH     16
#define HD     64
#define MTOT   (BB*NN)   // 8192

// Scratch (device globals: allocation-free rule)
__device__ float g_q[(size_t)BB*NH*NN*HD];
__device__ float g_k[(size_t)BB*NH*NN*HD];
__device__ float g_v[(size_t)BB*NH*NN*HD];
__device__ float g_ctx[(size_t)MTOT*DMODEL];

__device__ __forceinline__ float to_tf32(float x) {
    float r;
    asm("cvt.rna.tf32.f32 %0, %1;" : "=f"(r) : "f"(x));
    return r;
}

// D += A(16x8,row) * B(8x8,col)   fp32 accum, tf32 operands (bits in fp32 regs)
__device__ __forceinline__ void mma_tf32(float c[4], float a0, float a1, float a2, float a3,
                                         float b0, float b1) {
    asm("mma.sync.aligned.m16n8k8.row.col.f32.tf32.tf32.f32 "
        "{%0,%1,%2,%3},{%4,%5,%6,%7},{%8,%9},{%0,%1,%2,%3};"
        : "+f"(c[0]), "+f"(c[1]), "+f"(c[2]), "+f"(c[3])
        : "r"(__float_as_uint(a0)), "r"(__float_as_uint(a1)),
          "r"(__float_as_uint(a2)), "r"(__float_as_uint(a3)),
          "r"(__float_as_uint(b0)), "r"(__float_as_uint(b1)));
}

// ---------------------------------------------------------------------------
// TF32 tensor-core GEMM. C tile 128x128, K-tile 16, 256 thr = 8 warps (2x4),
// warp tile 64x32 = 4x4 frags of m16n8k8. Smem double-buffered, 1 sync/tile.
// mode 0: A=X, W per blockIdx.z (Wq/Wk/Wv), scatter to g_q/g_k/g_v [b,h,n,d]
// mode 1: A=g_ctx, W=W0, out = A@W + bias
// ---------------------------------------------------------------------------
__global__ __launch_bounds__(256, 2)
void gemm_tc(const float* __restrict__ Xp,
             const float* __restrict__ W0,
             const float* __restrict__ W1,
             const float* __restrict__ W2,
             const float* __restrict__ bias,
             float* __restrict__ outp,
             int mode)
{
    __shared__ float As[2][128][20];   // [m][k], pad 20 (A-frag pattern conflict-free)
    __shared__ float Bs[2][16][136];   // [k][n], pad 136 (B-frag pattern conflict-free)

    const int tid  = threadIdx.x;
    const int lane = tid & 31;
    const int warp = tid >> 5;
    const int wm   = warp >> 2;        // 0..1
    const int wn   = warp & 3;         // 0..3
    const int qr   = lane >> 2;        // 0..7
    const int qi   = lane & 3;         // 0..3
    const int bx   = blockIdx.x;
    const int by   = blockIdx.y;
    const int z    = blockIdx.z;

    const float* A = (mode == 0) ? Xp : (const float*)g_ctx;
    const float* W = (mode == 0) ? ((z == 0) ? W0 : (z == 1) ? W1 : W2) : W0;

    const float* Abase = A + (size_t)by * 128 * D_IN;
    const float* Bbase = W + bx * 128;

    float c[4][4][4];
#pragma unroll
    for (int mf = 0; mf < 4; mf++)
#pragma unroll
        for (int nf = 0; nf < 4; nf++)
#pragma unroll
            for (int k = 0; k < 4; k++) c[mf][nf][k] = 0.f;

    // global-load index precompute (2 float4 each for A and B per thread)
    const int aRow0 = tid >> 2,            aCg0 = (tid & 3) * 4;
    const int aRow1 = (tid + 256) >> 2,    aCg1 = aCg0;
    const int bRow0 = tid >> 5,            bC0  = (tid & 31) * 4;
    const int bRow1 = (tid + 256) >> 5,    bC1  = bC0;

    float4 pa[2], pb[2];
    // preload tile 0 -> buf 0
    pa[0] = *(const float4*)(Abase + (size_t)aRow0 * D_IN + aCg0);
    pa[1] = *(const float4*)(Abase + (size_t)aRow1 * D_IN + aCg1);
    pb[0] = *(const float4*)(Bbase + (size_t)bRow0 * DMODEL + bC0);
    pb[1] = *(const float4*)(Bbase + (size_t)bRow1 * DMODEL + bC1);
    {
        float4 t;
        t.x=to_tf32(pa[0].x); t.y=to_tf32(pa[0].y); t.z=to_tf32(pa[0].z); t.w=to_tf32(pa[0].w);
        *(float4*)&As[0][aRow0][aCg0] = t;
        t.x=to_tf32(pa[1].x); t.y=to_tf32(pa[1].y); t.z=to_tf32(pa[1].z); t.w=to_tf32(pa[1].w);
        *(float4*)&As[0][aRow1][aCg1] = t;
        t.x=to_tf32(pb[0].x); t.y=to_tf32(pb[0].y); t.z=to_tf32(pb[0].z); t.w=to_tf32(pb[0].w);
        *(float4*)&Bs[0][bRow0][bC0] = t;
        t.x=to_tf32(pb[1].x); t.y=to_tf32(pb[1].y); t.z=to_tf32(pb[1].z); t.w=to_tf32(pb[1].w);
        *(float4*)&Bs[0][bRow1][bC1] = t;
    }
    __syncthreads();

    const int KT = D_IN / 16;  // 64
    for (int kt = 0; kt < KT; kt++) {
        const int buf = kt & 1;
        if (kt < KT - 1) {
            const int ko = (kt + 1) * 16;
            pa[0] = *(const float4*)(Abase + (size_t)aRow0 * D_IN + ko + aCg0);
            pa[1] = *(const float4*)(Abase + (size_t)aRow1 * D_IN + ko + aCg1);
            pb[0] = *(const float4*)(Bbase + (size_t)(ko + bRow0) * DMODEL + bC0);
            pb[1] = *(const float4*)(Bbase + (size_t)(ko + bRow1) * DMODEL + bC1);
        }
#pragma unroll
        for (int ks = 0; ks < 2; ks++) {
            const int k0 = ks * 8;
            float a[4][4], b[4][2];
#pragma unroll
            for (int mf = 0; mf < 4; mf++) {
                const int r0 = wm * 64 + mf * 16 + qr;
                a[mf][0] = As[buf][r0][k0 + qi];
                a[mf][1] = As[buf][r0 + 8][k0 + qi];
                a[mf][2] = As[buf][r0][k0 + qi + 4];
                a[mf][3] = As[buf][r0 + 8][k0 + qi + 4];
            }
#pragma unroll
            for (int nf = 0; nf < 4; nf++) {
                const int cB = wn * 32 + nf * 8 + qr;
                b[nf][0] = Bs[buf][k0 + qi][cB];
                b[nf][1] = Bs[buf][k0 + qi + 4][cB];
            }
#pragma unroll
            for (int mf = 0; mf < 4; mf++)
#pragma unroll
                for (int nf = 0; nf < 4; nf++)
                    mma_tf32(c[mf][nf], a[mf][0], a[mf][1], a[mf][2], a[mf][3],
                             b[nf][0], b[nf][1]);
        }
        if (kt < KT - 1) {
            const int nb = buf ^ 1;
            float4 t;
            t.x=to_tf32(pa[0].x); t.y=to_tf32(pa[0].y); t.z=to_tf32(pa[0].z); t.w=to_tf32(pa[0].w);
            *(float4*)&As[nb][aRow0][aCg0] = t;
            t.x=to_tf32(pa[1].x); t.y=to_tf32(pa[1].y); t.z=to_tf32(pa[1].z); t.w=to_tf32(pa[1].w);
            *(float4*)&As[nb][aRow1][aCg1] = t;
            t.x=to_tf32(pb[0].x); t.y=to_tf32(pb[0].y); t.z=to_tf32(pb[0].z); t.w=to_tf32(pb[0].w);
            *(float4*)&Bs[nb][bRow0][bC0] = t;
            t.x=to_tf32(pb[1].x); t.y=to_tf32(pb[1].y); t.z=to_tf32(pb[1].z); t.w=to_tf32(pb[1].w);
            *(float4*)&Bs[nb][bRow1][bC1] = t;
            __syncthreads();
        }
    }

    // epilogue
    if (mode == 0) {
        float* O = (z == 0) ? g_q : (z == 1) ? g_k : g_v;
#pragma unroll
        for (int mf = 0; mf < 4; mf++)
#pragma unroll
            for (int nf = 0; nf < 4; nf++)
#pragma unroll
                for (int ci = 0; ci < 4; ci++) {
                    const int m = by * 128 + wm * 64 + mf * 16 + qr + ((ci >= 2) ? 8 : 0);
                    const int col = bx * 128 + wn * 32 + nf * 8 + 2 * qi + (ci & 1);
                    const int b_ = m >> 11, n_ = m & (NN - 1);
                    const int h_ = col >> 6, d_ = col & (HD - 1);
                    O[(((size_t)(b_ * NH + h_)) * NN + n_) * HD + d_] = c[mf][nf][ci];
                }
    } else {
#pragma unroll
        for (int mf = 0; mf < 4; mf++)
#pragma unroll
            for (int nf = 0; nf < 4; nf++)
#pragma unroll
                for (int ci = 0; ci < 4; ci++) {
                    const int m = by * 128 + wm * 64 + mf * 16 + qr + ((ci >= 2) ? 8 : 0);
                    const int col = bx * 128 + wn * 32 + nf * 8 + 2 * qi + (ci & 1);
                    outp[(size_t)m * DMODEL + col] = c[mf][nf][ci] + bias[col];
                }
    }
}

// ---------------------------------------------------------------------------
// Flash attention (causal), tensor cores. 128 thr = 4 warps; warp owns 16
// q-rows. S and PV via m16n8k8 tf32 mma. K buffer reused for P. Dynamic smem.
// ---------------------------------------------------------------------------
#define QS_STRIDE 68
#define KP_STRIDE 68
#define VS_STRIDE 72

__global__ __launch_bounds__(128, 4)
void attn_tc()
{
    extern __shared__ float sm[];
    float* Qs  = sm;                       // [64][68]  (A-frag pattern)
    float* KPs = sm + 64 * QS_STRIDE;      // [64][68]  K (B-frag), then P (A-frag)
    float* Vs  = sm + 2 * 64 * QS_STRIDE;  // [64][72]  (B-frag pattern)

    const int tid  = threadIdx.x;
    const int lane = tid & 31;
    const int w    = tid >> 5;             // 0..3
    const int qr   = lane >> 2;
    const int qi   = lane & 3;
    const int qt   = blockIdx.x;
    const int bh   = blockIdx.y;

    const float* Qg = g_q + ((size_t)bh * NN + qt * 64) * HD;
    const float* Kg = g_k + (size_t)bh * NN * HD;
    const float* Vg = g_v + (size_t)bh * NN * HD;

    // Q tile, pre-scaled by 1/sqrt(64), rounded to tf32
#pragma unroll
    for (int p = 0; p < 32; p++) {
        const int li = p * 128 + tid;
        Qs[(li >> 6) * QS_STRIDE + (li & 63)] = to_tf32(Qg[li] * 0.125f);
    }

    float m0 = -1e30f, m1 = -1e30f, l0 = 0.f, l1 = 0.f;
    float o[8][4];
#pragma unroll
    for (int nf = 0; nf < 8; nf++)
#pragma unroll
        for (int ci = 0; ci < 4; ci++) o[nf][ci] = 0.f;

    for (int kt = 0; kt <= qt; kt++) {
        __syncthreads();   // prior PV reads done (and Q visible at kt=0)
        const float* Ktg = Kg + (size_t)kt * 64 * HD;
        const float* Vtg = Vg + (size_t)kt * 64 * HD;
#pragma unroll
        for (int p = 0; p < 32; p++) {
            const int li = p * 128 + tid;
            const int r = li >> 6, d = li & 63;
            KPs[r * KP_STRIDE + d] = to_tf32(Ktg[li]);
            Vs[r * VS_STRIDE + d]  = to_tf32(Vtg[li]);
        }
        __syncthreads();

        // ---- S = Q K^T (m16 x n64, k=d=64) ----
        float s[8][4];
#pragma unroll
        for (int nf = 0; nf < 8; nf++)
#pragma unroll
            for (int ci = 0; ci < 4; ci++) s[nf][ci] = 0.f;

        const int ar = w * 16 + qr;
#pragma unroll
        for (int ks = 0; ks < 8; ks++) {
            const int k0 = ks * 8;
            const float a0 = Qs[ar * QS_STRIDE + k0 + qi];
            const float a1 = Qs[(ar + 8) * QS_STRIDE + k0 + qi];
            const float a2 = Qs[ar * QS_STRIDE + k0 + qi + 4];
            const float a3 = Qs[(ar + 8) * QS_STRIDE + k0 + qi + 4];
#pragma unroll
            for (int nf = 0; nf < 8; nf++) {
                const float b0 = KPs[(nf * 8 + qr) * KP_STRIDE + k0 + qi];
                const float b1 = KPs[(nf * 8 + qr) * KP_STRIDE + k0 + qi + 4];
                mma_tf32(s[nf], a0, a1, a2, a3, b0, b1);
            }
        }

        // causal mask on diagonal tile (local coords; tile offsets cancel)
        if (kt == qt) {
            const int r0 = w * 16 + qr, r1 = r0 + 8;
#pragma unroll
            for (int nf = 0; nf < 8; nf++) {
                const int cb = nf * 8 + 2 * qi;
                if (cb     > r0) s[nf][0] = -1e30f;
                if (cb + 1 > r0) s[nf][1] = -1e30f;
                if (cb     > r1) s[nf][2] = -1e30f;
                if (cb + 1 > r1) s[nf][3] = -1e30f;
            }
        }

        // ---- online softmax (rows owned by lane-quads) ----
        float mx0 = -1e30f, mx1 = -1e30f;
#pragma unroll
        for (int nf = 0; nf < 8; nf++) {
            mx0 = fmaxf(mx0, fmaxf(s[nf][0], s[nf][1]));
            mx1 = fmaxf(mx1, fmaxf(s[nf][2], s[nf][3]));
        }
        mx0 = fmaxf(mx0, __shfl_xor_sync(0xffffffffu, mx0, 1));
        mx0 = fmaxf(mx0, __shfl_xor_sync(0xffffffffu, mx0, 2));
        mx1 = fmaxf(mx1, __shfl_xor_sync(0xffffffffu, mx1, 1));
        mx1 = fmaxf(mx1, __shfl_xor_sync(0xffffffffu, mx1, 2));

        const float mn0 = fmaxf(m0, mx0), mn1 = fmaxf(m1, mx1);
        const float cf0 = __expf(m0 - mn0), cf1 = __expf(m1 - mn1);
        m0 = mn0; m1 = mn1;

        float rs0 = 0.f, rs1 = 0.f;
#pragma unroll
        for (int nf = 0; nf < 8; nf++) {
            s[nf][0] = __expf(s[nf][0] - mn0); rs0 += s[nf][0];
            s[nf][1] = __expf(s[nf][1] - mn0); rs0 += s[nf][1];
            s[nf][2] = __expf(s[nf][2] - mn1); rs1 += s[nf][2];
            s[nf][3] = __expf(s[nf][3] - mn1); rs1 += s[nf][3];
        }
        rs0 += __shfl_xor_sync(0xffffffffu, rs0, 1);
        rs0 += __shfl_xor_sync(0xffffffffu, rs0, 2);
        rs1 += __shfl_xor_sync(0xffffffffu, rs1, 1);
        rs1 += __shfl_xor_sync(0xffffffffu, rs1, 2);
        l0 = l0 * cf0 + rs0;
        l1 = l1 * cf1 + rs1;
#pragma unroll
        for (int nf = 0; nf < 8; nf++) {
            o[nf][0] *= cf0; o[nf][1] *= cf0;
            o[nf][2] *= cf1; o[nf][3] *= cf1;
        }

        // ---- P -> smem (reuse K buffer), tf32-rounded ----
        __syncthreads();   // all warps finished reading K
        {
            const int r0 = w * 16 + qr;
#pragma unroll
            for (int nf = 0; nf < 8; nf++) {
                const int cb = nf * 8 + 2 * qi;
                KPs[r0 * KP_STRIDE + cb]           = to_tf32(s[nf][0]);
                KPs[r0 * KP_STRIDE + cb + 1]       = to_tf32(s[nf][1]);
                KPs[(r0 + 8) * KP_STRIDE + cb]     = to_tf32(s[nf][2]);
                KPs[(r0 + 8) * KP_STRIDE + cb + 1] = to_tf32(s[nf][3]);
            }
        }
        __syncwarp();      // own-warp rows only -> warp-level visibility suffices

        // ---- O += P V (m16 x n64(d), k=64 tokens) ----
        const int pr = w * 16 + qr;
#pragma unroll
        for (int ks = 0; ks < 8; ks++) {
            const int k0 = ks * 8;
            const float a0 = KPs[pr * KP_STRIDE + k0 + qi];
            const float a1 = KPs[(pr + 8) * KP_STRIDE + k0 + qi];
            const float a2 = KPs[pr * KP_STRIDE + k0 + qi + 4];
            const float a3 = KPs[(pr + 8) * KP_STRIDE + k0 + qi + 4];
#pragma unroll
            for (int nf = 0; nf < 8; nf++) {
                const float b0 = Vs[(k0 + qi) * VS_STRIDE + nf * 8 + qr];
                const float b1 = Vs[(k0 + qi + 4) * VS_STRIDE + nf * 8 + qr];
                mma_tf32(o[nf], a0, a1, a2, a3, b0, b1);
            }
        }
    }

    // normalize + write ctx [b, n, h*64+d]
    const int b_ = bh >> 4, h_ = bh & 15;
    const float inv0 = 1.f / l0, inv1 = 1.f / l1;
#pragma unroll
    for (int nf = 0; nf < 8; nf++) {
        const int n0 = qt * 64 + w * 16 + qr;
        const int cb = h_ * 64 + nf * 8 + 2 * qi;
        g_ctx[((size_t)(b_ * NN + n0)) * DMODEL + cb]           = o[nf][0] * inv0;
        g_ctx[((size_t)(b_ * NN + n0)) * DMODEL + cb + 1]       = o[nf][1] * inv0;
        g_ctx[((size_t)(b_ * NN + n0 + 8)) * DMODEL + cb]       = o[nf][2] * inv1;
        g_ctx[((size_t)(b_ * NN + n0 + 8)) * DMODEL + cb + 1]   = o[nf][3] * inv1;
    }
}

#define ATTN_SMEM ((2 * 64 * QS_STRIDE + 64 * VS_STRIDE) * 4)  // 53248 B

// ---------------------------------------------------------------------------
extern "C" void kernel_launch(void* const* d_in, const int* in_sizes, int n_in,
                              void* d_out, int out_size)
{
    const float* x  = (const float*)d_in[0];
    const float* Wq = (const float*)d_in[1];
    const float* Wk = (const float*)d_in[2];
    const float* Wv = (const float*)d_in[3];
    const float* Wo = (const float*)d_in[4];
    const float* bo = (const float*)d_in[5];
    float* out = (float*)d_out;

    cudaFuncSetAttribute(attn_tc, cudaFuncAttributeMaxDynamicSharedMemorySize, ATTN_SMEM);

    // QKV projections -> g_q/g_k/g_v [b,h,n,d]
    gemm_tc<<<dim3(8, 64, 3), 256>>>(x, Wq, Wk, Wv, nullptr, nullptr, 0);
    // causal flash attention
    attn_tc<<<dim3(32, 64), 128, ATTN_SMEM>>>();
    // output projection + bias
    gemm_tc<<<dim3(8, 64, 1), 256>>>(nullptr, Wo, nullptr, nullptr, bo, out, 1);
}

// round 7
// speedup vs baseline: 3.1658x; 1.0019x over previous
#include <cuda_runtime.h>
#include <cstdint>

#define D_IN   1024
#define DMODEL 1024
#define BB     4
#define NN     2048
#define NH     16
#define HD     64
#define MTOT   (BB*NN)   // 8192

// Scratch (device globals: allocation-free rule)
__device__ float g_q[(size_t)BB*NH*NN*HD];
__device__ float g_k[(size_t)BB*NH*NN*HD];
__device__ float g_v[(size_t)BB*NH*NN*HD];
__device__ float g_ctx[(size_t)MTOT*DMODEL];

__device__ __forceinline__ float to_tf32(float x) {
    float r;
    asm("cvt.rna.tf32.f32 %0, %1;" : "=f"(r) : "f"(x));
    return r;
}

// D += A(16x8,row) * B(8x8,col)   fp32 accum, tf32 operands (bits in fp32 regs)
__device__ __forceinline__ void mma_tf32(float c[4], float a0, float a1, float a2, float a3,
                                         float b0, float b1) {
    asm("mma.sync.aligned.m16n8k8.row.col.f32.tf32.tf32.f32 "
        "{%0,%1,%2,%3},{%4,%5,%6,%7},{%8,%9},{%0,%1,%2,%3};"
        : "+f"(c[0]), "+f"(c[1]), "+f"(c[2]), "+f"(c[3])
        : "r"(__float_as_uint(a0)), "r"(__float_as_uint(a1)),
          "r"(__float_as_uint(a2)), "r"(__float_as_uint(a3)),
          "r"(__float_as_uint(b0)), "r"(__float_as_uint(b1)));
}

// ---------------------------------------------------------------------------
// TF32 tensor-core GEMM. C tile 128x128, K-tile 16, 256 thr = 8 warps (2x4),
// warp tile 64x32 = 4x4 frags of m16n8k8. Smem double-buffered, 1 sync/tile.
// mode 0: A=X, W per blockIdx.z (Wq/Wk/Wv), scatter to g_q/g_k/g_v [b,h,n,d]
// mode 1: A=g_ctx, W=W0, out = A@W + bias
// ---------------------------------------------------------------------------
__global__ __launch_bounds__(256, 2)
void gemm_tc(const float* __restrict__ Xp,
             const float* __restrict__ W0,
             const float* __restrict__ W1,
             const float* __restrict__ W2,
             const float* __restrict__ bias,
             float* __restrict__ outp,
             int mode)
{
    __shared__ float As[2][128][20];   // [m][k], pad 20 (A-frag pattern conflict-free)
    __shared__ float Bs[2][16][136];   // [k][n], pad 136 (B-frag pattern conflict-free)

    const int tid  = threadIdx.x;
    const int lane = tid & 31;
    const int warp = tid >> 5;
    const int wm   = warp >> 2;        // 0..1
    const int wn   = warp & 3;         // 0..3
    const int qr   = lane >> 2;        // 0..7
    const int qi   = lane & 3;         // 0..3
    const int bx   = blockIdx.x;
    const int by   = blockIdx.y;
    const int z    = blockIdx.z;

    const float* A = (mode == 0) ? Xp : (const float*)g_ctx;
    const float* W = (mode == 0) ? ((z == 0) ? W0 : (z == 1) ? W1 : W2) : W0;

    const float* Abase = A + (size_t)by * 128 * D_IN;
    const float* Bbase = W + bx * 128;

    float c[4][4][4];
#pragma unroll
    for (int mf = 0; mf < 4; mf++)
#pragma unroll
        for (int nf = 0; nf < 4; nf++)
#pragma unroll
            for (int k = 0; k < 4; k++) c[mf][nf][k] = 0.f;

    // global-load index precompute (2 float4 each for A and B per thread)
    const int aRow0 = tid >> 2,            aCg0 = (tid & 3) * 4;
    const int aRow1 = (tid + 256) >> 2,    aCg1 = aCg0;
    const int bRow0 = tid >> 5,            bC0  = (tid & 31) * 4;
    const int bRow1 = (tid + 256) >> 5,    bC1  = bC0;

    float4 pa[2], pb[2];
    // preload tile 0 -> buf 0
    pa[0] = *(const float4*)(Abase + (size_t)aRow0 * D_IN + aCg0);
    pa[1] = *(const float4*)(Abase + (size_t)aRow1 * D_IN + aCg1);
    pb[0] = *(const float4*)(Bbase + (size_t)bRow0 * DMODEL + bC0);
    pb[1] = *(const float4*)(Bbase + (size_t)bRow1 * DMODEL + bC1);
    {
        float4 t;
        t.x=to_tf32(pa[0].x); t.y=to_tf32(pa[0].y); t.z=to_tf32(pa[0].z); t.w=to_tf32(pa[0].w);
        *(float4*)&As[0][aRow0][aCg0] = t;
        t.x=to_tf32(pa[1].x); t.y=to_tf32(pa[1].y); t.z=to_tf32(pa[1].z); t.w=to_tf32(pa[1].w);
        *(float4*)&As[0][aRow1][aCg1] = t;
        t.x=to_tf32(pb[0].x); t.y=to_tf32(pb[0].y); t.z=to_tf32(pb[0].z); t.w=to_tf32(pb[0].w);
        *(float4*)&Bs[0][bRow0][bC0] = t;
        t.x=to_tf32(pb[1].x); t.y=to_tf32(pb[1].y); t.z=to_tf32(pb[1].z); t.w=to_tf32(pb[1].w);
        *(float4*)&Bs[0][bRow1][bC1] = t;
    }
    __syncthreads();

    const int KT = D_IN / 16;  // 64
    for (int kt = 0; kt < KT; kt++) {
        const int buf = kt & 1;
        if (kt < KT - 1) {
            const int ko = (kt + 1) * 16;
            pa[0] = *(const float4*)(Abase + (size_t)aRow0 * D_IN + ko + aCg0);
            pa[1] = *(const float4*)(Abase + (size_t)aRow1 * D_IN + ko + aCg1);
            pb[0] = *(const float4*)(Bbase + (size_t)(ko + bRow0) * DMODEL + bC0);
            pb[1] = *(const float4*)(Bbase + (size_t)(ko + bRow1) * DMODEL + bC1);
        }
#pragma unroll
        for (int ks = 0; ks < 2; ks++) {
            const int k0 = ks * 8;
            float a[4][4], b[4][2];
#pragma unroll
            for (int mf = 0; mf < 4; mf++) {
                const int r0 = wm * 64 + mf * 16 + qr;
                a[mf][0] = As[buf][r0][k0 + qi];
                a[mf][1] = As[buf][r0 + 8][k0 + qi];
                a[mf][2] = As[buf][r0][k0 + qi + 4];
                a[mf][3] = As[buf][r0 + 8][k0 + qi + 4];
            }
#pragma unroll
            for (int nf = 0; nf < 4; nf++) {
                const int cB = wn * 32 + nf * 8 + qr;
                b[nf][0] = Bs[buf][k0 + qi][cB];
                b[nf][1] = Bs[buf][k0 + qi + 4][cB];
            }
#pragma unroll
            for (int mf = 0; mf < 4; mf++)
#pragma unroll
                for (int nf = 0; nf < 4; nf++)
                    mma_tf32(c[mf][nf], a[mf][0], a[mf][1], a[mf][2], a[mf][3],
                             b[nf][0], b[nf][1]);
        }
        if (kt < KT - 1) {
            const int nb = buf ^ 1;
            float4 t;
            t.x=to_tf32(pa[0].x); t.y=to_tf32(pa[0].y); t.z=to_tf32(pa[0].z); t.w=to_tf32(pa[0].w);
            *(float4*)&As[nb][aRow0][aCg0] = t;
            t.x=to_tf32(pa[1].x); t.y=to_tf32(pa[1].y); t.z=to_tf32(pa[1].z); t.w=to_tf32(pa[1].w);
            *(float4*)&As[nb][aRow1][aCg1] = t;
            t.x=to_tf32(pb[0].x); t.y=to_tf32(pb[0].y); t.z=to_tf32(pb[0].z); t.w=to_tf32(pb[0].w);
            *(float4*)&Bs[nb][bRow0][bC0] = t;
            t.x=to_tf32(pb[1].x); t.y=to_tf32(pb[1].y); t.z=to_tf32(pb[1].z); t.w=to_tf32(pb[1].w);
            *(float4*)&Bs[nb][bRow1][bC1] = t;
            __syncthreads();
        }
    }

    // epilogue
    if (mode == 0) {
        float* O = (z == 0) ? g_q : (z == 1) ? g_k : g_v;
#pragma unroll
        for (int mf = 0; mf < 4; mf++)
#pragma unroll
            for (int nf = 0; nf < 4; nf++)
#pragma unroll
                for (int ci = 0; ci < 4; ci++) {
                    const int m = by * 128 + wm * 64 + mf * 16 + qr + ((ci >= 2) ? 8 : 0);
                    const int col = bx * 128 + wn * 32 + nf * 8 + 2 * qi + (ci & 1);
                    const int b_ = m >> 11, n_ = m & (NN - 1);
                    const int h_ = col >> 6, d_ = col & (HD - 1);
                    O[(((size_t)(b_ * NH + h_)) * NN + n_) * HD + d_] = c[mf][nf][ci];
                }
    } else {
#pragma unroll
        for (int mf = 0; mf < 4; mf++)
#pragma unroll
            for (int nf = 0; nf < 4; nf++)
#pragma unroll
                for (int ci = 0; ci < 4; ci++) {
                    const int m = by * 128 + wm * 64 + mf * 16 + qr + ((ci >= 2) ? 8 : 0);
                    const int col = bx * 128 + wn * 32 + nf * 8 + 2 * qi + (ci & 1);
                    outp[(size_t)m * DMODEL + col] = c[mf][nf][ci] + bias[col];
                }
    }
}

// ---------------------------------------------------------------------------
// Flash attention (causal), tensor cores. 128 thr = 4 warps; warp owns 16
// q-rows. S and PV via m16n8k8 tf32 mma. K buffer reused for P. Dynamic smem.
// ---------------------------------------------------------------------------
#define QS_STRIDE 68
#define KP_STRIDE 68
#define VS_STRIDE 72

__global__ __launch_bounds__(128, 4)
void attn_tc()
{
    extern __shared__ float sm[];
    float* Qs  = sm;                       // [64][68]  (A-frag pattern)
    float* KPs = sm + 64 * QS_STRIDE;      // [64][68]  K (B-frag), then P (A-frag)
    float* Vs  = sm + 2 * 64 * QS_STRIDE;  // [64][72]  (B-frag pattern)

    const int tid  = threadIdx.x;
    const int lane = tid & 31;
    const int w    = tid >> 5;             // 0..3
    const int qr   = lane >> 2;
    const int qi   = lane & 3;
    const int qt   = blockIdx.x;
    const int bh   = blockIdx.y;

    const float* Qg = g_q + ((size_t)bh * NN + qt * 64) * HD;
    const float* Kg = g_k + (size_t)bh * NN * HD;
    const float* Vg = g_v + (size_t)bh * NN * HD;

    // Q tile, pre-scaled by 1/sqrt(64), rounded to tf32
#pragma unroll
    for (int p = 0; p < 32; p++) {
        const int li = p * 128 + tid;
        Qs[(li >> 6) * QS_STRIDE + (li & 63)] = to_tf32(Qg[li] * 0.125f);
    }

    float m0 = -1e30f, m1 = -1e30f, l0 = 0.f, l1 = 0.f;
    float o[8][4];
#pragma unroll
    for (int nf = 0; nf < 8; nf++)
#pragma unroll
        for (int ci = 0; ci < 4; ci++) o[nf][ci] = 0.f;

    for (int kt = 0; kt <= qt; kt++) {
        __syncthreads();   // prior PV reads done (and Q visible at kt=0)
        const float* Ktg = Kg + (size_t)kt * 64 * HD;
        const float* Vtg = Vg + (size_t)kt * 64 * HD;
#pragma unroll
        for (int p = 0; p < 32; p++) {
            const int li = p * 128 + tid;
            const int r = li >> 6, d = li & 63;
            KPs[r * KP_STRIDE + d] = to_tf32(Ktg[li]);
            Vs[r * VS_STRIDE + d]  = to_tf32(Vtg[li]);
        }
        __syncthreads();

        // ---- S = Q K^T (m16 x n64, k=d=64) ----
        float s[8][4];
#pragma unroll
        for (int nf = 0; nf < 8; nf++)
#pragma unroll
            for (int ci = 0; ci < 4; ci++) s[nf][ci] = 0.f;

        const int ar = w * 16 + qr;
#pragma unroll
        for (int ks = 0; ks < 8; ks++) {
            const int k0 = ks * 8;
            const float a0 = Qs[ar * QS_STRIDE + k0 + qi];
            const float a1 = Qs[(ar + 8) * QS_STRIDE + k0 + qi];
            const float a2 = Qs[ar * QS_STRIDE + k0 + qi + 4];
            const float a3 = Qs[(ar + 8) * QS_STRIDE + k0 + qi + 4];
#pragma unroll
            for (int nf = 0; nf < 8; nf++) {
                const float b0 = KPs[(nf * 8 + qr) * KP_STRIDE + k0 + qi];
                const float b1 = KPs[(nf * 8 + qr) * KP_STRIDE + k0 + qi + 4];
                mma_tf32(s[nf], a0, a1, a2, a3, b0, b1);
            }
        }

        // causal mask on diagonal tile (local coords; tile offsets cancel)
        if (kt == qt) {
            const int r0 = w * 16 + qr, r1 = r0 + 8;
#pragma unroll
            for (int nf = 0; nf < 8; nf++) {
                const int cb = nf * 8 + 2 * qi;
                if (cb     > r0) s[nf][0] = -1e30f;
                if (cb + 1 > r0) s[nf][1] = -1e30f;
                if (cb     > r1) s[nf][2] = -1e30f;
                if (cb + 1 > r1) s[nf][3] = -1e30f;
            }
        }

        // ---- online softmax (rows owned by lane-quads) ----
        float mx0 = -1e30f, mx1 = -1e30f;
#pragma unroll
        for (int nf = 0; nf < 8; nf++) {
            mx0 = fmaxf(mx0, fmaxf(s[nf][0], s[nf][1]));
            mx1 = fmaxf(mx1, fmaxf(s[nf][2], s[nf][3]));
        }
        mx0 = fmaxf(mx0, __shfl_xor_sync(0xffffffffu, mx0, 1));
        mx0 = fmaxf(mx0, __shfl_xor_sync(0xffffffffu, mx0, 2));
        mx1 = fmaxf(mx1, __shfl_xor_sync(0xffffffffu, mx1, 1));
        mx1 = fmaxf(mx1, __shfl_xor_sync(0xffffffffu, mx1, 2));

        const float mn0 = fmaxf(m0, mx0), mn1 = fmaxf(m1, mx1);
        const float cf0 = __expf(m0 - mn0), cf1 = __expf(m1 - mn1);
        m0 = mn0; m1 = mn1;

        float rs0 = 0.f, rs1 = 0.f;
#pragma unroll
        for (int nf = 0; nf < 8; nf++) {
            s[nf][0] = __expf(s[nf][0] - mn0); rs0 += s[nf][0];
            s[nf][1] = __expf(s[nf][1] - mn0); rs0 += s[nf][1];
            s[nf][2] = __expf(s[nf][2] - mn1); rs1 += s[nf][2];
            s[nf][3] = __expf(s[nf][3] - mn1); rs1 += s[nf][3];
        }
        rs0 += __shfl_xor_sync(0xffffffffu, rs0, 1);
        rs0 += __shfl_xor_sync(0xffffffffu, rs0, 2);
        rs1 += __shfl_xor_sync(0xffffffffu, rs1, 1);
        rs1 += __shfl_xor_sync(0xffffffffu, rs1, 2);
        l0 = l0 * cf0 + rs0;
        l1 = l1 * cf1 + rs1;
#pragma unroll
        for (int nf = 0; nf < 8; nf++) {
            o[nf][0] *= cf0; o[nf][1] *= cf0;
            o[nf][2] *= cf1; o[nf][3] *= cf1;
        }

        // ---- P -> smem (reuse K buffer), tf32-rounded ----
        __syncthreads();   // all warps finished reading K
        {
            const int r0 = w * 16 + qr;
#pragma unroll
            for (int nf = 0; nf < 8; nf++) {
                const int cb = nf * 8 + 2 * qi;
                KPs[r0 * KP_STRIDE + cb]           = to_tf32(s[nf][0]);
                KPs[r0 * KP_STRIDE + cb + 1]       = to_tf32(s[nf][1]);
                KPs[(r0 + 8) * KP_STRIDE + cb]     = to_tf32(s[nf][2]);
                KPs[(r0 + 8) * KP_STRIDE + cb + 1] = to_tf32(s[nf][3]);
            }
        }
        __syncwarp();      // own-warp rows only -> warp-level visibility suffices

        // ---- O += P V (m16 x n64(d), k=64 tokens) ----
        const int pr = w * 16 + qr;
#pragma unroll
        for (int ks = 0; ks < 8; ks++) {
            const int k0 = ks * 8;
            const float a0 = KPs[pr * KP_STRIDE + k0 + qi];
            const float a1 = KPs[(pr + 8) * KP_STRIDE + k0 + qi];
            const float a2 = KPs[pr * KP_STRIDE + k0 + qi + 4];
            const float a3 = KPs[(pr + 8) * KP_STRIDE + k0 + qi + 4];
#pragma unroll
            for (int nf = 0; nf < 8; nf++) {
                const float b0 = Vs[(k0 + qi) * VS_STRIDE + nf * 8 + qr];
                const float b1 = Vs[(k0 + qi + 4) * VS_STRIDE + nf * 8 + qr];
                mma_tf32(o[nf], a0, a1, a2, a3, b0, b1);
            }
        }
    }

    // normalize + write ctx [b, n, h*64+d]
    const int b_ = bh >> 4, h_ = bh & 15;
    const float inv0 = 1.f / l0, inv1 = 1.f / l1;
#pragma unroll
    for (int nf = 0; nf < 8; nf++) {
        const int n0 = qt * 64 + w * 16 + qr;
        const int cb = h_ * 64 + nf * 8 + 2 * qi;
        g_ctx[((size_t)(b_ * NN + n0)) * DMODEL + cb]           = o[nf][0] * inv0;
        g_ctx[((size_t)(b_ * NN + n0)) * DMODEL + cb + 1]       = o[nf][1] * inv0;
        g_ctx[((size_t)(b_ * NN + n0 + 8)) * DMODEL + cb]       = o[nf][2] * inv1;
        g_ctx[((size_t)(b_ * NN + n0 + 8)) * DMODEL + cb + 1]   = o[nf][3] * inv1;
    }
}

#define ATTN_SMEM ((2 * 64 * QS_STRIDE + 64 * VS_STRIDE) * 4)  // 53248 B

// ---------------------------------------------------------------------------
extern "C" void kernel_launch(void* const* d_in, const int* in_sizes, int n_in,
                              void* d_out, int out_size)
{
    const float* x  = (const float*)d_in[0];
    const float* Wq = (const float*)d_in[1];
    const float* Wk = (const float*)d_in[2];
    const float* Wv = (const float*)d_in[3];
    const float* Wo = (const float*)d_in[4];
    const float* bo = (const float*)d_in[5];
    float* out = (float*)d_out;

    cudaFuncSetAttribute(attn_tc, cudaFuncAttributeMaxDynamicSharedMemorySize, ATTN_SMEM);

    // QKV projections -> g_q/g_k/g_v [b,h,n,d]
    gemm_tc<<<dim3(8, 64, 3), 256>>>(x, Wq, Wk, Wv, nullptr, nullptr, 0);
    // causal flash attention
    attn_tc<<<dim3(32, 64), 128, ATTN_SMEM>>>();
    // output projection + bias
    gemm_tc<<<dim3(8, 64, 1), 256>>>(nullptr, Wo, nullptr, nullptr, bo, out, 1);
}